// round 2
// baseline (speedup 1.0000x reference)
#include <cuda_runtime.h>

// Problem constants (fixed by the reference)
#define BB       8
#define N_SMALL  12288
#define N_FULL   24576
#define CC       256
#define KK       4096

// Scratch: final image-row index per output row (or -1 -> zero row)
__device__ int g_row[BB * N_FULL];

// ---------------------------------------------------------------------------
// Kernel 1: per-batch chain resolution in shared memory.
//   src[v] starts as identity; executing src[t_k] = src[f_k] for k = K-1..0
//   (the scan order of the reference) mirrors the value-copy scan exactly.
//   Then convert src -> image row via inv[] built from mask_idx.
//   One CTA per batch, 192 KB dynamic smem.
//
//   NOTE: JAX default config canonicalizes int64 -> int32, so mask_idx and
//   order arrive as int32 on device.
// ---------------------------------------------------------------------------
__global__ void __launch_bounds__(1024, 1)
resolve_kernel(const int* __restrict__ mask_idx,
               const int* __restrict__ order)
{
    extern __shared__ int smem[];
    int*  src   = smem;              // [N_FULL]
    int*  aux   = smem + N_FULL;     // [N_FULL]: first pairs (2K ints), then inv
    int2* pairs = (int2*)aux;        // [K]

    const int b   = blockIdx.x;
    const int tid = threadIdx.x;
    const int nt  = blockDim.x;

    // Phase A (parallel): identity src, stage order pairs as int2
    for (int v = tid; v < N_FULL; v += nt) src[v] = v;
    const int* of = order + b * 2 * KK;   // row 0 = f
    const int* ot = of + KK;              // row 1 = t
    for (int k = tid; k < KK; k += nt)
        pairs[k] = make_int2(of[k], ot[k]);
    __syncthreads();

    // Phase B (single thread): sequential provenance propagation.
    // No register-carried dependency between iterations -> pipelines in LSU.
    if (tid == 0) {
        #pragma unroll 8
        for (int k = KK - 1; k >= 0; --k) {
            int2 p = pairs[k];
            src[p.y] = src[p.x];
        }
    }
    __syncthreads();

    // Phase C (parallel): build inv[] in aux (pairs no longer needed)
    for (int v = tid; v < N_FULL; v += nt) aux[v] = -1;
    __syncthreads();
    const int* mi = mask_idx + b * N_SMALL;
    for (int i = tid; i < N_SMALL; i += nt) aux[mi[i]] = i;
    __syncthreads();

    // Phase D (parallel): emit final row mapping
    int* grow = g_row + b * N_FULL;
    for (int v = tid; v < N_FULL; v += nt) grow[v] = aux[src[v]];
}

// ---------------------------------------------------------------------------
// Kernel 2: fully parallel vectorized row gather.
//   out[b, v, :] = row >= 0 ? images[b, row, :] : 0
//   One float4 per thread; consecutive threads cover consecutive quads of a
//   row -> fully coalesced 1 KB row reads/writes.
// ---------------------------------------------------------------------------
__global__ void gather_kernel(const float4* __restrict__ img,
                              float4* __restrict__ out)
{
    const int idx    = blockIdx.x * blockDim.x + threadIdx.x; // float4 index
    const int rowIdx = idx >> 6;          // 64 float4 per row (C=256)
    const int q      = idx & 63;
    const int b      = rowIdx / N_FULL;
    const int row    = __ldg(&g_row[rowIdx]);

    float4 val = make_float4(0.f, 0.f, 0.f, 0.f);
    if (row >= 0)
        val = img[((size_t)b * N_SMALL + row) * 64 + q];
    out[idx] = val;
}

extern "C" void kernel_launch(void* const* d_in, const int* in_sizes, int n_in,
                              void* d_out, int out_size)
{
    const float* images   = (const float*)d_in[0];
    const int*   mask_idx = (const int*)d_in[1];
    const int*   order    = (const int*)d_in[2];
    float* out = (float*)d_out;

    // 192 KB dynamic smem for the resolve kernel (idempotent attribute set)
    cudaFuncSetAttribute(resolve_kernel,
                         cudaFuncAttributeMaxDynamicSharedMemorySize,
                         2 * N_FULL * (int)sizeof(int));

    resolve_kernel<<<BB, 1024, 2 * N_FULL * (int)sizeof(int)>>>(mask_idx, order);

    const int total4 = BB * N_FULL * (CC / 4);   // 12,582,912 float4
    gather_kernel<<<total4 / 256, 256>>>((const float4*)images, (float4*)out);
}

// round 3
// speedup vs baseline: 2.1352x; 2.1352x over previous
#include <cuda_runtime.h>

#define BB       8
#define N_SMALL  12288
#define N_FULL   24576
#define CC       256
#define KK       4096
#define NT       1024
#define VPT      (N_FULL / NT)   // 24 vertices per thread

// Scratch: final image-row index per output row (or -1 -> zero row)
__device__ int g_row[BB * N_FULL];

// ---------------------------------------------------------------------------
// Kernel 1: PARALLEL per-batch chain resolution.
//
// Reference semantics (per batch), in processing order p = 0..K-1
// (p corresponds to order column k = K-1-p):   src[T[p]] = src[F[p]]
//
// Final value of vertex v = chase(v, K):
//   find write to v with largest time p < P; if none -> v,
//   else -> chase(F[p], p).          (time bound strictly decreases)
//
// Build per-vertex write lists with a shared-memory counting sort, then all
// N_FULL vertices chase independently in parallel. Expected chain length
// ~1/(1-K/N) ~= 1.2 hops for random data.
// ---------------------------------------------------------------------------
__global__ void __launch_bounds__(NT, 1)
resolve_kernel(const int* __restrict__ mask_idx,
               const int* __restrict__ order)
{
    extern __shared__ int smem[];
    int* offs    = smem;                 // [N_FULL]  counts -> prefix -> ends; later inv
    int* Ts      = smem + N_FULL;        // [K] target per time p
    int* Fs      = Ts + KK;              // [K] source per time p
    int* list    = Fs + KK;              // [K] packed (p<<15)|f grouped by target
    int* scratch = list + KK;            // [32] warp partials for block scan

    const int b    = blockIdx.x;
    const int tid  = threadIdx.x;
    const int lane = tid & 31;
    const int wid  = tid >> 5;

    // ---- Phase A: stage pairs in processing order, zero counts ----
    const int* of = order + b * 2 * KK;   // row 0 = f
    const int* ot = of + KK;              // row 1 = t
    for (int p = tid; p < KK; p += NT) {
        Fs[p] = of[KK - 1 - p];
        Ts[p] = ot[KK - 1 - p];
    }
    for (int v = tid; v < N_FULL; v += NT) offs[v] = 0;
    __syncthreads();

    // ---- Phase B: count writes per target ----
    for (int p = tid; p < KK; p += NT) atomicAdd(&offs[Ts[p]], 1);
    __syncthreads();

    // ---- Phase C: in-place exclusive prefix scan of offs[N_FULL] ----
    {
        const int base = tid * VPT;
        int s = 0;
        #pragma unroll
        for (int i = 0; i < VPT; i++) s += offs[base + i];

        int incl = s;
        #pragma unroll
        for (int d = 1; d < 32; d <<= 1) {
            int n = __shfl_up_sync(0xFFFFFFFFu, incl, d);
            if (lane >= d) incl += n;
        }
        if (lane == 31) scratch[wid] = incl;
        __syncthreads();
        if (wid == 0) {
            int w  = scratch[lane];
            int wi = w;
            #pragma unroll
            for (int d = 1; d < 32; d <<= 1) {
                int n = __shfl_up_sync(0xFFFFFFFFu, wi, d);
                if (lane >= d) wi += n;
            }
            scratch[lane] = wi - w;     // exclusive warp offset
        }
        __syncthreads();
        int run = scratch[wid] + incl - s;   // thread-exclusive base
        #pragma unroll
        for (int i = 0; i < VPT; i++) {
            int c = offs[base + i];
            offs[base + i] = run;
            run += c;
        }
    }
    __syncthreads();

    // ---- Phase D: scatter packed (p<<15)|f into per-target lists ----
    // After this, offs[v] = END of v's list; start = (v ? offs[v-1] : 0).
    for (int p = tid; p < KK; p += NT) {
        int pos = atomicAdd(&offs[Ts[p]], 1);
        list[pos] = (p << 15) | Fs[p];
    }
    __syncthreads();

    // ---- Phase E: parallel provenance chase; results in registers ----
    int r[VPT];
    #pragma unroll
    for (int j = 0; j < VPT; j++) {
        int cur = j * NT + tid;
        int P   = KK;
        for (;;) {
            int lo = cur ? offs[cur - 1] : 0;
            int hi = offs[cur];
            int best = -1;
            for (int e = lo; e < hi; e++) {
                int pv = list[e];
                if ((pv >> 15) < P && pv > best) best = pv;
            }
            if (best < 0) break;
            cur = best & 0x7FFF;
            P   = best >> 15;
        }
        r[j] = cur;
    }
    __syncthreads();

    // ---- Phase F: reuse offs as inv[]: full-vertex -> image row ----
    for (int v = tid; v < N_FULL; v += NT) offs[v] = -1;
    __syncthreads();
    const int* mi = mask_idx + b * N_SMALL;
    for (int i = tid; i < N_SMALL; i += NT) offs[mi[i]] = i;
    __syncthreads();

    int* grow = g_row + b * N_FULL;
    #pragma unroll
    for (int j = 0; j < VPT; j++)
        grow[j * NT + tid] = offs[r[j]];
}

// ---------------------------------------------------------------------------
// Kernel 2: vectorized row gather, 4 x float4 (64B) per thread.
//   out[b, v, :] = row >= 0 ? images[b, row, :] : 0
//   Streaming stores (__stcs) keep L2 capacity for the reused image rows.
// ---------------------------------------------------------------------------
__global__ void gather_kernel(const float4* __restrict__ img,
                              float4* __restrict__ out)
{
    const int t      = blockIdx.x * blockDim.x + threadIdx.x;
    const int idx4   = t * 4;              // first float4 index
    const int rowIdx = idx4 >> 6;          // 64 float4 per row (C=256)
    const int q      = idx4 & 63;
    const int b      = rowIdx / N_FULL;
    const int row    = __ldg(&g_row[rowIdx]);

    float4 v0, v1, v2, v3;
    if (row >= 0) {
        const float4* src = img + ((size_t)b * N_SMALL + row) * 64 + q;
        v0 = __ldg(src + 0);
        v1 = __ldg(src + 1);
        v2 = __ldg(src + 2);
        v3 = __ldg(src + 3);
    } else {
        v0 = v1 = v2 = v3 = make_float4(0.f, 0.f, 0.f, 0.f);
    }
    __stcs(out + idx4 + 0, v0);
    __stcs(out + idx4 + 1, v1);
    __stcs(out + idx4 + 2, v2);
    __stcs(out + idx4 + 3, v3);
}

extern "C" void kernel_launch(void* const* d_in, const int* in_sizes, int n_in,
                              void* d_out, int out_size)
{
    const float* images   = (const float*)d_in[0];
    const int*   mask_idx = (const int*)d_in[1];
    const int*   order    = (const int*)d_in[2];
    float* out = (float*)d_out;

    const int smem_bytes = (N_FULL + 3 * KK + 32) * (int)sizeof(int); // ~148 KB
    cudaFuncSetAttribute(resolve_kernel,
                         cudaFuncAttributeMaxDynamicSharedMemorySize,
                         smem_bytes);

    resolve_kernel<<<BB, NT, smem_bytes>>>(mask_idx, order);

    const int total4 = BB * N_FULL * (CC / 4);   // 12,582,912 float4
    gather_kernel<<<total4 / 4 / 256, 256>>>((const float4*)images, (float4*)out);
}